// round 3
// baseline (speedup 1.0000x reference)
#include <cuda_runtime.h>
#include <stdint.h>

#define D_FEAT   256
#define D4       (D_FEAT / 4)     // 64 float4 per x row
#define OUTW     (2 * D_FEAT)     // 512 floats per output row
#define MAX_N    32768
#define MAX_E    400000

// Scratch (no cudaMalloc allowed) — device globals
__device__ int   g_deg[MAX_N];
__device__ float g_dis[MAX_N];
__device__ int   g_cnt;
__device__ int   g_idx64;          // 1 if edge_index is int64, 0 if int32
__device__ int2  g_cedge[MAX_E];   // compacted (src, dst)
__device__ float g_cw[MAX_E];      // compacted weight

// Fetch edge endpoint honoring detected index dtype.
__device__ __forceinline__ int load_src(const void* ei, int E, int i, int is64) {
    return is64 ? (int)((const long long*)ei)[i] : ((const int*)ei)[i];
}
__device__ __forceinline__ int load_dst(const void* ei, int E, int i, int is64) {
    return is64 ? (int)((const long long*)ei)[E + i] : ((const int*)ei)[E + i];
}

// ---------------------------------------------------------------------------
// 0. detect index dtype: if any of the first K int64-interpreted values is out
//    of [0, n), the underlying data must be int32.
__global__ void k_detect(const void* ei, int E, int n) {
    __shared__ int bad;
    if (threadIdx.x == 0) bad = 0;
    __syncthreads();
    const long long* e64 = (const long long*)ei;
    int K = min(E, 2048);
    for (int i = threadIdx.x; i < K; i += blockDim.x) {
        long long v = e64[i];
        if (v < 0 || v >= (long long)n) bad = 1;
    }
    __syncthreads();
    if (threadIdx.x == 0) {
        g_idx64 = bad ? 0 : 1;
        g_cnt = 0;
    }
}

// 1. zero degree counters
__global__ void k_zero(int n) {
    int i = blockIdx.x * blockDim.x + threadIdx.x;
    if (i < n) g_deg[i] = 0;
}

// 2. deg[src] += 1 over all edges
__global__ void k_count_deg(const void* __restrict__ ei, int E) {
    int i = blockIdx.x * blockDim.x + threadIdx.x;
    if (i < E) {
        int src = load_src(ei, E, i, g_idx64);
        atomicAdd(&g_deg[src], 1);
    }
}

// 3. dis[i] = deg>0 ? rsqrt(deg) : 0
__global__ void k_compute_dis(int n) {
    int i = blockIdx.x * blockDim.x + threadIdx.x;
    if (i < n) {
        int d = g_deg[i];
        g_dis[i] = (d > 0) ? rsqrtf((float)d) : 0.0f;
    }
}

// 4. compact edges that actually contribute: dst < batch and w != 0
__global__ void k_compact(const void* __restrict__ ei, int E, int batch) {
    int i = blockIdx.x * blockDim.x + threadIdx.x;
    if (i >= E) return;
    int is64 = g_idx64;
    int dst = load_dst(ei, E, i, is64);
    if (dst >= batch) return;
    int src = load_src(ei, E, i, is64);
    float w = g_dis[src] * g_dis[dst];
    if (w == 0.0f) return;
    int pos = atomicAdd(&g_cnt, 1);
    g_cedge[pos] = make_int2(src, dst);
    g_cw[pos] = w;
}

// 5. out[i, 0:256] = x[i]; out[i, 256:512] = 0  (for i < batch)
__global__ void k_init_out(const float4* __restrict__ x4, float4* __restrict__ out4,
                           int batch) {
    int idx = blockIdx.x * blockDim.x + threadIdx.x;
    int total = batch * (OUTW / 4);            // 128 float4 per out row
    if (idx < total) {
        int row = idx >> 7;
        int col = idx & 127;
        out4[idx] = (col < D4) ? __ldg(&x4[row * D4 + col])
                               : make_float4(0.f, 0.f, 0.f, 0.f);
    }
}

__device__ __forceinline__ void red_add_v4(float* p, float4 v) {
    asm volatile("red.global.add.v4.f32 [%0], {%1, %2, %3, %4};"
                 :: "l"(p), "f"(v.x), "f"(v.y), "f"(v.z), "f"(v.w)
                 : "memory");
}

// 6. persistent scatter: one warp per compacted edge, grid-stride
__global__ void k_scatter(const float4* __restrict__ x4, float* __restrict__ out) {
    int nwarps = (gridDim.x * blockDim.x) >> 5;
    int gwarp  = (blockIdx.x * blockDim.x + threadIdx.x) >> 5;
    int lane   = threadIdx.x & 31;
    int cnt    = g_cnt;

    for (int e = gwarp; e < cnt; e += nwarps) {
        int2  ed = g_cedge[e];
        float w  = g_cw[e];
        const float4* xs = x4 + (size_t)ed.x * D4;
        float* o = out + (size_t)ed.y * OUTW + D_FEAT;

        #pragma unroll
        for (int j = lane; j < D4; j += 32) {
            float4 v = __ldg(&xs[j]);
            float4 r = make_float4(w * v.x, w * v.y, w * v.z, w * v.w);
            red_add_v4(&o[j * 4], r);
        }
    }
}

// ---------------------------------------------------------------------------
extern "C" void kernel_launch(void* const* d_in, const int* in_sizes, int n_in,
                              void* d_out, int out_size) {
    // Identify inputs by element count (robust to metadata ordering):
    //   x          : largest (N * 256 floats)
    //   edge_index : second largest (2 * E elements)
    //   batch_size : 1 element (ignored; derived from out_size)
    int ix = 0, ie = -1;
    for (int i = 1; i < n_in; i++)
        if (in_sizes[i] > in_sizes[ix]) ix = i;
    for (int i = 0; i < n_in; i++) {
        if (i == ix || in_sizes[i] <= 1) continue;
        if (ie < 0 || in_sizes[i] > in_sizes[ie]) ie = i;
    }
    if (ie < 0) ie = (ix == 0) ? 1 : 0;

    const float* x  = (const float*)d_in[ix];
    const void*  ei = d_in[ie];

    int n     = in_sizes[ix] / D_FEAT;         // 20000
    int E     = in_sizes[ie] / 2;              // 320000
    int batch = out_size / OUTW;               // 4096

    const float4* x4   = (const float4*)x;
    float4*       out4 = (float4*)d_out;
    float*        out  = (float*)d_out;

    k_detect<<<1, 256>>>(ei, E, n);
    k_zero<<<(n + 255) / 256, 256>>>(n);
    k_count_deg<<<(E + 255) / 256, 256>>>(ei, E);
    k_compute_dis<<<(n + 255) / 256, 256>>>(n);
    k_compact<<<(E + 255) / 256, 256>>>(ei, E, batch);

    int total = batch * (OUTW / 4);
    k_init_out<<<(total + 255) / 256, 256>>>(x4, out4, batch);

    // persistent scatter: 4 CTAs/SM * 148 SMs
    k_scatter<<<592, 256>>>(x4, out);
}

// round 4
// speedup vs baseline: 1.3954x; 1.3954x over previous
#include <cuda_runtime.h>
#include <stdint.h>

#define D_FEAT   256
#define D4       (D_FEAT / 4)     // 64 float4 per x row
#define OUTW     (2 * D_FEAT)     // 512 floats per output row
#define MAX_N    32768
#define MAX_B    16384
#define MAX_E    400000

// Scratch (no cudaMalloc allowed) — device globals
__device__ int   g_deg[MAX_N];
__device__ float g_dis[MAX_N];
__device__ int   g_hist[MAX_B];
__device__ int   g_rowptr[MAX_B + 1];
__device__ int   g_cursor[MAX_B];
__device__ int   g_idx64;            // 1 if edge_index is int64, 0 if int32
__device__ int   g_csr_src[MAX_E];
__device__ float g_csr_w[MAX_E];

__device__ __forceinline__ int load_idx(const void* ei, int i, int is64) {
    return is64 ? (int)((const long long*)ei)[i] : ((const int*)ei)[i];
}

// ---------------------------------------------------------------------------
// 1. zero deg + hist; block 0 additionally detects index dtype.
__global__ void k_prep(const void* __restrict__ ei, int E, int n, int batch) {
    int i = blockIdx.x * blockDim.x + threadIdx.x;
    if (i < n) g_deg[i] = 0;
    if (i < batch) g_hist[i] = 0;
    if (blockIdx.x == 0) {
        __shared__ int bad;
        if (threadIdx.x == 0) bad = 0;
        __syncthreads();
        const long long* e64 = (const long long*)ei;
        int K = min(E, 2048);
        for (int t = threadIdx.x; t < K; t += blockDim.x) {
            long long v = e64[t];
            if (v < 0 || v >= (long long)n) bad = 1;
        }
        __syncthreads();
        if (threadIdx.x == 0) g_idx64 = bad ? 0 : 1;
    }
}

// 2. deg[src]++ for all edges; hist[dst]++ for dst < batch.
__global__ void k_count(const void* __restrict__ ei, int E, int batch) {
    int i = blockIdx.x * blockDim.x + threadIdx.x;
    if (i >= E) return;
    int is64 = g_idx64;
    int src = load_idx(ei, i, is64);
    int dst = load_idx(ei, E + i, is64);
    atomicAdd(&g_deg[src], 1);
    if (dst < batch) atomicAdd(&g_hist[dst], 1);
}

// 3. block 0: exclusive scan of hist -> rowptr, cursor; blocks>=1: dis = deg^-1/2.
__global__ void k_scan_dis(int n, int batch) {
    if (blockIdx.x == 0) {
        __shared__ int s[1024];
        int tid = threadIdx.x;
        int run = 0;
        for (int base = 0; base < batch; base += 4096) {
            int v[4], sum4 = 0;
            #pragma unroll
            for (int k = 0; k < 4; k++) {
                int idx = base + tid * 4 + k;
                v[k] = (idx < batch) ? g_hist[idx] : 0;
                sum4 += v[k];
            }
            s[tid] = sum4;
            __syncthreads();
            for (int off = 1; off < 1024; off <<= 1) {
                int t = (tid >= off) ? s[tid - off] : 0;
                __syncthreads();
                s[tid] += t;
                __syncthreads();
            }
            int excl = s[tid] - sum4;
            int pos = run + excl;
            #pragma unroll
            for (int k = 0; k < 4; k++) {
                int idx = base + tid * 4 + k;
                if (idx < batch) {
                    g_rowptr[idx] = pos;
                    g_cursor[idx] = pos;
                    pos += v[k];
                }
            }
            int total = s[1023];
            __syncthreads();
            run += total;
        }
        if (tid == 0) g_rowptr[batch] = run;
    } else {
        int i = (blockIdx.x - 1) * blockDim.x + threadIdx.x;
        if (i < n) {
            int d = g_deg[i];
            g_dis[i] = (d > 0) ? rsqrtf((float)d) : 0.0f;
        }
    }
}

// 4. fill CSR: for each edge with dst < batch, append (src, w) to row dst.
__global__ void k_fill(const void* __restrict__ ei, int E, int batch) {
    int i = blockIdx.x * blockDim.x + threadIdx.x;
    if (i >= E) return;
    int is64 = g_idx64;
    int dst = load_idx(ei, E + i, is64);
    if (dst >= batch) return;
    int src = load_idx(ei, i, is64);
    float w = g_dis[src] * g_dis[dst];
    int pos = atomicAdd(&g_cursor[dst], 1);
    g_csr_src[pos] = src;
    g_csr_w[pos] = w;
}

// 5. gather: one warp per output row. Accumulate in registers; write each output
//    element exactly once (copy half + aggregated half).
__global__ void __launch_bounds__(256) k_gather(const float4* __restrict__ x4,
                                                float4* __restrict__ out4,
                                                int batch) {
    int row  = (blockIdx.x * blockDim.x + threadIdx.x) >> 5;
    int lane = threadIdx.x & 31;
    if (row >= batch) return;

    int beg = g_rowptr[row];
    int end = g_rowptr[row + 1];

    float4 a0 = make_float4(0.f, 0.f, 0.f, 0.f);
    float4 a1 = make_float4(0.f, 0.f, 0.f, 0.f);

    for (int base = beg; base < end; base += 32) {
        int e = base + lane;
        int cnt = min(32, end - base);
        int   psrc = (e < end) ? g_csr_src[e] : 0;
        float pw   = (e < end) ? g_csr_w[e]   : 0.0f;

        for (int t = 0; t < cnt; t++) {
            int   s  = __shfl_sync(0xffffffff, psrc, t);
            float ww = __shfl_sync(0xffffffff, pw, t);
            const float4* xs = x4 + (size_t)s * D4;
            float4 v0 = __ldg(&xs[lane]);
            float4 v1 = __ldg(&xs[lane + 32]);
            a0.x += ww * v0.x; a0.y += ww * v0.y; a0.z += ww * v0.z; a0.w += ww * v0.w;
            a1.x += ww * v1.x; a1.y += ww * v1.y; a1.z += ww * v1.z; a1.w += ww * v1.w;
        }
    }

    const float4* xd = x4 + (size_t)row * D4;
    float4* o = out4 + (size_t)row * (OUTW / 4);
    o[lane]      = __ldg(&xd[lane]);
    o[lane + 32] = __ldg(&xd[lane + 32]);
    o[lane + 64] = a0;
    o[lane + 96] = a1;
}

// ---------------------------------------------------------------------------
extern "C" void kernel_launch(void* const* d_in, const int* in_sizes, int n_in,
                              void* d_out, int out_size) {
    // Identify inputs by element count (robust to metadata ordering):
    //   x: largest; edge_index: second largest; batch_size scalar ignored.
    int ix = 0, ie = -1;
    for (int i = 1; i < n_in; i++)
        if (in_sizes[i] > in_sizes[ix]) ix = i;
    for (int i = 0; i < n_in; i++) {
        if (i == ix || in_sizes[i] <= 1) continue;
        if (ie < 0 || in_sizes[i] > in_sizes[ie]) ie = i;
    }
    if (ie < 0) ie = (ix == 0) ? 1 : 0;

    const float* x  = (const float*)d_in[ix];
    const void*  ei = d_in[ie];

    int n     = in_sizes[ix] / D_FEAT;         // 20000
    int E     = in_sizes[ie] / 2;              // 320000
    int batch = out_size / OUTW;               // 4096

    const float4* x4   = (const float4*)x;
    float4*       out4 = (float4*)d_out;

    int mx = (n > batch) ? n : batch;
    k_prep<<<(mx + 255) / 256, 256>>>(ei, E, n, batch);
    k_count<<<(E + 255) / 256, 256>>>(ei, E, batch);
    k_scan_dis<<<1 + (n + 1023) / 1024, 1024>>>(n, batch);
    k_fill<<<(E + 255) / 256, 256>>>(ei, E, batch);

    long long gthreads = (long long)batch * 32;
    k_gather<<<(int)((gthreads + 255) / 256), 256>>>(x4, out4, batch);
}

// round 5
// speedup vs baseline: 1.9034x; 1.3640x over previous
#include <cuda_runtime.h>
#include <stdint.h>

#define D_FEAT   256
#define D4       (D_FEAT / 4)     // 64 float4 per x row
#define OUTW     (2 * D_FEAT)     // 512 floats per output row
#define MAX_N    32768
#define MAX_B    8192
#define CAP      128              // slots per destination row (mean deg ~16)
#define MAX_SP   65536            // spill capacity (normally 0 used)

// Scratch (no cudaMalloc allowed) — device globals
__device__ int   g_deg[MAX_N];
__device__ int   g_cntrow[MAX_B];
__device__ int   g_idx64;                  // 1 if edge_index is int64, 0 if int32
__device__ int   g_spill;
__device__ int   g_slots[MAX_B * CAP];     // src per (dst, slot)
__device__ int2  g_sp_edge[MAX_SP];

__device__ __forceinline__ int load_idx(const void* ei, int i, int is64) {
    return is64 ? (int)((const long long*)ei)[i] : ((const int*)ei)[i];
}

// ---------------------------------------------------------------------------
// 1. zero deg + per-row counters + spill; block 0 detects index dtype.
__global__ void k_prep(const void* __restrict__ ei, int E, int n, int batch) {
    int i = blockIdx.x * blockDim.x + threadIdx.x;
    if (i < n) g_deg[i] = 0;
    if (i < batch) g_cntrow[i] = 0;
    if (blockIdx.x == 0) {
        __shared__ int bad;
        if (threadIdx.x == 0) bad = 0;
        __syncthreads();
        const long long* e64 = (const long long*)ei;
        int K = min(E, 2048);
        for (int t = threadIdx.x; t < K; t += blockDim.x) {
            long long v = e64[t];
            if (v < 0 || v >= (long long)n) bad = 1;
        }
        __syncthreads();
        if (threadIdx.x == 0) {
            g_idx64 = bad ? 0 : 1;
            g_spill = 0;
        }
    }
}

// 2. single edge pass: deg[src]++; bucket src into slots of dst (dst < batch).
__global__ void k_build(const void* __restrict__ ei, int E, int batch) {
    int i = blockIdx.x * blockDim.x + threadIdx.x;
    if (i >= E) return;
    int is64 = g_idx64;
    int src = load_idx(ei, i, is64);
    int dst = load_idx(ei, E + i, is64);
    atomicAdd(&g_deg[src], 1);
    if (dst < batch) {
        int slot = atomicAdd(&g_cntrow[dst], 1);
        if (slot < CAP) {
            g_slots[dst * CAP + slot] = src;
        } else {
            int p = atomicAdd(&g_spill, 1);
            if (p < MAX_SP) g_sp_edge[p] = make_int2(src, dst);
        }
    }
}

// 3. gather: one warp per output row; weights computed from deg on the fly.
//    Writes every output element exactly once (x copy + aggregated half).
__global__ void __launch_bounds__(256) k_gather(const float4* __restrict__ x4,
                                                float4* __restrict__ out4,
                                                int batch) {
    int row  = (blockIdx.x * blockDim.x + threadIdx.x) >> 5;
    int lane = threadIdx.x & 31;
    if (row >= batch) return;

    int m = g_cntrow[row];
    if (m > CAP) m = CAP;
    int dr = g_deg[row];
    float disr = (dr > 0) ? rsqrtf((float)dr) : 0.0f;

    float4 a0 = make_float4(0.f, 0.f, 0.f, 0.f);
    float4 a1 = make_float4(0.f, 0.f, 0.f, 0.f);

    const int* srow = g_slots + row * CAP;
    for (int base = 0; base < m; base += 32) {
        int e = base + lane;
        int cnt = min(32, m - base);
        int   psrc = 0;
        float pw   = 0.0f;
        if (e < m) {
            psrc = srow[e];
            pw = rsqrtf((float)g_deg[psrc]) * disr;   // deg[src] >= 1 always
        }
        for (int t = 0; t < cnt; t++) {
            int   s  = __shfl_sync(0xffffffff, psrc, t);
            float ww = __shfl_sync(0xffffffff, pw, t);
            const float4* xs = x4 + (size_t)s * D4;
            float4 v0 = __ldg(&xs[lane]);
            float4 v1 = __ldg(&xs[lane + 32]);
            a0.x += ww * v0.x; a0.y += ww * v0.y; a0.z += ww * v0.z; a0.w += ww * v0.w;
            a1.x += ww * v1.x; a1.y += ww * v1.y; a1.z += ww * v1.z; a1.w += ww * v1.w;
        }
    }

    const float4* xd = x4 + (size_t)row * D4;
    float4* o = out4 + (size_t)row * (OUTW / 4);
    o[lane]      = __ldg(&xd[lane]);
    o[lane + 32] = __ldg(&xd[lane + 32]);
    o[lane + 64] = a0;
    o[lane + 96] = a1;
}

__device__ __forceinline__ void red_add_v4(float* p, float4 v) {
    asm volatile("red.global.add.v4.f32 [%0], {%1, %2, %3, %4};"
                 :: "l"(p), "f"(v.x), "f"(v.y), "f"(v.z), "f"(v.w)
                 : "memory");
}

// 4. spill handler (normally zero iterations): RED overflow edges into out.
__global__ void k_spill(const float4* __restrict__ x4, float* __restrict__ out) {
    int nwarps = (gridDim.x * blockDim.x) >> 5;
    int gwarp  = (blockIdx.x * blockDim.x + threadIdx.x) >> 5;
    int lane   = threadIdx.x & 31;
    int cnt = g_spill;
    if (cnt > MAX_SP) cnt = MAX_SP;

    for (int e = gwarp; e < cnt; e += nwarps) {
        int2 ed = g_sp_edge[e];
        int dd = g_deg[ed.y];
        float w = rsqrtf((float)g_deg[ed.x]) * ((dd > 0) ? rsqrtf((float)dd) : 0.0f);
        const float4* xs = x4 + (size_t)ed.x * D4;
        float* o = out + (size_t)ed.y * OUTW + D_FEAT;
        #pragma unroll
        for (int j = lane; j < D4; j += 32) {
            float4 v = __ldg(&xs[j]);
            float4 r = make_float4(w * v.x, w * v.y, w * v.z, w * v.w);
            red_add_v4(&o[j * 4], r);
        }
    }
}

// ---------------------------------------------------------------------------
extern "C" void kernel_launch(void* const* d_in, const int* in_sizes, int n_in,
                              void* d_out, int out_size) {
    // Identify inputs by element count (robust to metadata ordering).
    int ix = 0, ie = -1;
    for (int i = 1; i < n_in; i++)
        if (in_sizes[i] > in_sizes[ix]) ix = i;
    for (int i = 0; i < n_in; i++) {
        if (i == ix || in_sizes[i] <= 1) continue;
        if (ie < 0 || in_sizes[i] > in_sizes[ie]) ie = i;
    }
    if (ie < 0) ie = (ix == 0) ? 1 : 0;

    const float* x  = (const float*)d_in[ix];
    const void*  ei = d_in[ie];

    int n     = in_sizes[ix] / D_FEAT;         // 20000
    int E     = in_sizes[ie] / 2;              // 320000
    int batch = out_size / OUTW;               // 4096

    const float4* x4   = (const float4*)x;
    float4*       out4 = (float4*)d_out;
    float*        out  = (float*)d_out;

    int mx = (n > batch) ? n : batch;
    k_prep<<<(mx + 255) / 256, 256>>>(ei, E, n, batch);
    k_build<<<(E + 255) / 256, 256>>>(ei, E, batch);

    long long gthreads = (long long)batch * 32;
    k_gather<<<(int)((gthreads + 255) / 256), 256>>>(x4, out4, batch);
    k_spill<<<64, 256>>>(x4, out);
}

// round 6
// speedup vs baseline: 1.9557x; 1.0275x over previous
#include <cuda_runtime.h>
#include <stdint.h>

#define D_FEAT   256
#define D4       (D_FEAT / 4)     // 64 float4 per x row
#define OUTW     (2 * D_FEAT)     // 512 floats per output row
#define MAX_N    32768
#define MAX_B    8192
#define CAP      128              // slots per destination row (mean deg ~16, max ~45)
#define MAX_SP   65536            // spill capacity (normally 0 used)

// Scratch (no cudaMalloc allowed) — device globals
__device__ int   g_deg[MAX_N];
__device__ int   g_cntrow[MAX_B];
__device__ int   g_idx64;                  // 1 if edge_index is int64, 0 if int32
__device__ int   g_spill;
__device__ int   g_slots[MAX_B * CAP];     // src per (dst, slot)
__device__ int2  g_sp_edge[MAX_SP];

// ---------------------------------------------------------------------------
// 1. zero deg + per-row counters + spill; block 0 detects index dtype.
__global__ void k_prep(const void* __restrict__ ei, int E, int n, int batch) {
    int i = blockIdx.x * blockDim.x + threadIdx.x;
    if (i < n) g_deg[i] = 0;
    if (i < batch) g_cntrow[i] = 0;
    if (blockIdx.x == 0) {
        __shared__ int bad;
        if (threadIdx.x == 0) bad = 0;
        __syncthreads();
        const long long* e64 = (const long long*)ei;
        int K = min(E, 2048);
        for (int t = threadIdx.x; t < K; t += blockDim.x) {
            long long v = e64[t];
            if (v < 0 || v >= (long long)n) bad = 1;
        }
        __syncthreads();
        if (threadIdx.x == 0) {
            g_idx64 = bad ? 0 : 1;
            g_spill = 0;
        }
    }
}

// 2. single edge pass, 2 edges per thread: deg[src]++; bucket src into dst slots.
__global__ void k_build(const void* __restrict__ ei, int E, int batch) {
    int i2 = blockIdx.x * blockDim.x + threadIdx.x;   // pair index
    int base = i2 * 2;
    if (base >= E) return;
    int is64 = g_idx64;

    int s0, s1, d0, d1;
    int valid1 = (base + 1 < E);
    if (is64) {
        const long long* e64 = (const long long*)ei;
        if (valid1) {
            longlong2 sv = ((const longlong2*)e64)[i2];
            s0 = (int)sv.x; s1 = (int)sv.y;
            // dst stream starts at e64+E; E may be odd in general -> scalar loads
            d0 = (int)e64[E + base]; d1 = (int)e64[E + base + 1];
        } else {
            s0 = (int)e64[base]; d0 = (int)e64[E + base];
            s1 = 0; d1 = 0;
        }
    } else {
        const int* e32 = (const int*)ei;
        if (valid1) {
            int2 sv = ((const int2*)(e32))[i2];
            s0 = sv.x; s1 = sv.y;
            d0 = e32[E + base]; d1 = e32[E + base + 1];
        } else {
            s0 = e32[base]; d0 = e32[E + base];
            s1 = 0; d1 = 0;
        }
    }

    atomicAdd(&g_deg[s0], 1);
    if (d0 < batch) {
        int slot = atomicAdd(&g_cntrow[d0], 1);
        if (slot < CAP) g_slots[d0 * CAP + slot] = s0;
        else {
            int p = atomicAdd(&g_spill, 1);
            if (p < MAX_SP) g_sp_edge[p] = make_int2(s0, d0);
        }
    }
    if (valid1) {
        atomicAdd(&g_deg[s1], 1);
        if (d1 < batch) {
            int slot = atomicAdd(&g_cntrow[d1], 1);
            if (slot < CAP) g_slots[d1 * CAP + slot] = s1;
            else {
                int p = atomicAdd(&g_spill, 1);
                if (p < MAX_SP) g_sp_edge[p] = make_int2(s1, d1);
            }
        }
    }
}

// 3. gather: one warp per output row; weights computed from deg on the fly.
//    Rows that overflowed CAP additionally scan the spill list (normally never).
//    Writes every output element exactly once (x copy + aggregated half).
__global__ void __launch_bounds__(256) k_gather(const float4* __restrict__ x4,
                                                float4* __restrict__ out4,
                                                int batch) {
    int row  = (blockIdx.x * blockDim.x + threadIdx.x) >> 5;
    int lane = threadIdx.x & 31;
    if (row >= batch) return;

    int mraw = g_cntrow[row];
    int m = (mraw > CAP) ? CAP : mraw;
    int dr = g_deg[row];
    float disr = (dr > 0) ? rsqrtf((float)dr) : 0.0f;

    float4 a0 = make_float4(0.f, 0.f, 0.f, 0.f);
    float4 a1 = make_float4(0.f, 0.f, 0.f, 0.f);

    const int* srow = g_slots + row * CAP;
    for (int base = 0; base < m; base += 32) {
        int e = base + lane;
        int cnt = min(32, m - base);
        int   psrc = 0;
        float pw   = 0.0f;
        if (e < m) {
            psrc = srow[e];
            pw = rsqrtf((float)g_deg[psrc]) * disr;   // deg[src] >= 1 always
        }
        for (int t = 0; t < cnt; t++) {
            int   s  = __shfl_sync(0xffffffff, psrc, t);
            float ww = __shfl_sync(0xffffffff, pw, t);
            const float4* xs = x4 + (size_t)s * D4;
            float4 v0 = __ldg(&xs[lane]);
            float4 v1 = __ldg(&xs[lane + 32]);
            a0.x += ww * v0.x; a0.y += ww * v0.y; a0.z += ww * v0.z; a0.w += ww * v0.w;
            a1.x += ww * v1.x; a1.y += ww * v1.y; a1.z += ww * v1.z; a1.w += ww * v1.w;
        }
    }

    // Overflow path: this row's extra edges live in the spill list; only the
    // owning warp touches them, so there is no store/RED race. Never taken
    // unless a row exceeds CAP=128 neighbors.
    if (mraw > CAP) {
        int sp = g_spill;
        if (sp > MAX_SP) sp = MAX_SP;
        for (int base = 0; base < sp; base += 32) {
            int e = base + lane;
            int cnt = min(32, sp - base);
            int   psrc = 0;
            float pw   = 0.0f;
            if (e < sp) {
                int2 ed = g_sp_edge[e];
                if (ed.y == row) {
                    psrc = ed.x;
                    pw = rsqrtf((float)g_deg[psrc]) * disr;
                }
            }
            for (int t = 0; t < cnt; t++) {
                float ww = __shfl_sync(0xffffffff, pw, t);
                if (ww == 0.0f) continue;
                int s = __shfl_sync(0xffffffff, psrc, t);
                const float4* xs = x4 + (size_t)s * D4;
                float4 v0 = __ldg(&xs[lane]);
                float4 v1 = __ldg(&xs[lane + 32]);
                a0.x += ww * v0.x; a0.y += ww * v0.y; a0.z += ww * v0.z; a0.w += ww * v0.w;
                a1.x += ww * v1.x; a1.y += ww * v1.y; a1.z += ww * v1.z; a1.w += ww * v1.w;
            }
        }
    }

    const float4* xd = x4 + (size_t)row * D4;
    float4* o = out4 + (size_t)row * (OUTW / 4);
    o[lane]      = __ldg(&xd[lane]);
    o[lane + 32] = __ldg(&xd[lane + 32]);
    o[lane + 64] = a0;
    o[lane + 96] = a1;
}

// ---------------------------------------------------------------------------
extern "C" void kernel_launch(void* const* d_in, const int* in_sizes, int n_in,
                              void* d_out, int out_size) {
    // Identify inputs by element count (robust to metadata ordering).
    int ix = 0, ie = -1;
    for (int i = 1; i < n_in; i++)
        if (in_sizes[i] > in_sizes[ix]) ix = i;
    for (int i = 0; i < n_in; i++) {
        if (i == ix || in_sizes[i] <= 1) continue;
        if (ie < 0 || in_sizes[i] > in_sizes[ie]) ie = i;
    }
    if (ie < 0) ie = (ix == 0) ? 1 : 0;

    const float* x  = (const float*)d_in[ix];
    const void*  ei = d_in[ie];

    int n     = in_sizes[ix] / D_FEAT;         // 20000
    int E     = in_sizes[ie] / 2;              // 320000
    int batch = out_size / OUTW;               // 4096

    const float4* x4   = (const float4*)x;
    float4*       out4 = (float4*)d_out;

    int mx = (n > batch) ? n : batch;
    k_prep<<<(mx + 255) / 256, 256>>>(ei, E, n, batch);

    int pairs = (E + 1) / 2;
    k_build<<<(pairs + 255) / 256, 256>>>(ei, E, batch);

    long long gthreads = (long long)batch * 32;
    k_gather<<<(int)((gthreads + 255) / 256), 256>>>(x4, out4, batch);
}